// round 14
// baseline (speedup 1.0000x reference)
#include <cuda_runtime.h>
#include <cuda_bf16.h>
#include <math.h>

#define NBINS 128
#define NFREQ 64
#define NKERN 3
#define MLPH  64
#define KPB   28   // keys per block -> grid 293; 2 blocks/SM
#define TPB   256
#define JKEYS 7

typedef unsigned long long ull;

// Planar coefficient table: g_C[f][coord][bin], coord 0..6 =
//   [A0, A1c, A1s, A2c, A2s, A3c, A3s]
// +2 f of padding so distance-2 prefetch stays in-bounds.
__device__ float4 g_C4[(NFREQ + 2) * 7 * NBINS / 4];

__device__ __forceinline__ void fma2(ull& acc, ull a, ull b) {
    asm("fma.rn.f32x2 %0, %1, %2, %0;" : "+l"(acc) : "l"(a), "l"(b));
}
__device__ __forceinline__ ull dup2(float v) {
    ull r;
    asm("mov.b64 %0, {%1, %1};" : "=l"(r) : "f"(v));
    return r;
}
__device__ __forceinline__ ull pack2(float lo, float hi) {
    ull r;
    asm("mov.b64 %0, {%1, %2};" : "=l"(r) : "f"(lo), "f"(hi));
    return r;
}
__device__ __forceinline__ float2 unpack2(ull v) {
    float2 r;
    asm("mov.b64 {%0, %1}, %2;" : "=f"(r.x), "=f"(r.y) : "l"(v));
    return r;
}
__device__ __forceinline__ void pref_l1(const void* p) {
    asm volatile("prefetch.global.L1 [%0];" :: "l"(p));
}

// I_k(kappa) via Horner series in h2 = (kappa/2)^2, no divisions.
__global__ void precompute_fourier(const float* __restrict__ mu,
                                   const float* __restrict__ kappa,
                                   const float* __restrict__ weight,
                                   const float* __restrict__ ref_angles) {
    int idx = blockIdx.x * blockDim.x + threadIdx.x;
    if (idx >= NBINS * NFREQ) return;
    int b = idx / NFREQ;
    int f = idx % NFREQ;
    float C[7];
    #pragma unroll
    for (int i = 0; i < 7; i++) C[i] = 0.f;

    #pragma unroll
    for (int m = 0; m < NKERN; m++) {
        int off = (b * NFREQ + f) * NKERN + m;
        float kp = kappa[off];
        float w  = weight[off];
        float me = mu[off] + ref_angles[f];
        float h  = 0.5f * kp;
        float h2 = h * h;
        float ek = __expf(-kp);
        float P0 = fmaf(h2, fmaf(h2, fmaf(h2, fmaf(h2, fmaf(h2, fmaf(h2,
                    1.9290123e-6f, 6.9444444e-5f), 1.7361111e-3f), 2.7777778e-2f),
                    0.25f), 1.0f), 1.0f);
        float P1 = fmaf(h2, fmaf(h2, fmaf(h2, fmaf(h2, fmaf(h2, fmaf(h2,
                    2.7557319e-7f, 1.1574074e-5f), 3.4722222e-4f), 6.9444444e-3f),
                    8.3333333e-2f), 0.5f), 1.0f);
        float P2 = fmaf(h2, fmaf(h2, fmaf(h2, fmaf(h2, fmaf(h2, fmaf(h2,
                    3.4446e-8f, 1.6534392e-6f), 5.7870370e-5f), 1.3888889e-3f),
                    2.0833333e-2f), 1.6666667e-1f), 0.5f);
        float P3 = fmaf(h2, fmaf(h2, fmaf(h2, fmaf(h2, fmaf(h2, fmaf(h2,
                    3.83e-9f, 2.0667e-7f), 8.2671958e-6f), 2.3148148e-4f),
                    4.1666667e-3f), 4.1666667e-2f), 1.6666667e-1f);
        float I0 = P0;
        float I1 = h * P1;
        float I2 = h2 * P2;
        float I3 = h2 * h * P3;

        float cm, sm;
        __sincosf(me, &sm, &cm);
        float wek = w * ek;
        C[0] += wek * I0;
        float g1 = 2.f * wek * I1;
        C[1] += g1 * cm;
        C[2] += g1 * sm;
        float c2 = cm * cm - sm * sm;
        float s2 = 2.f * cm * sm;
        float g2 = 2.f * wek * I2;
        C[3] += g2 * c2;
        C[4] += g2 * s2;
        float c3 = c2 * cm - s2 * sm;
        float s3 = s2 * cm + c2 * sm;
        float g3 = 2.f * wek * I3;
        C[5] += g3 * c3;
        C[6] += g3 * s3;
    }
    float* gC = (float*)g_C4;
    #pragma unroll
    for (int c = 0; c < 7; c++)
        gC[(f * 7 + c) * NBINS + b] = C[c];
}

// dynamic smem (floats):
//   sl [28*128] @ 0, sl2 [28*128] @ 3584,
//   union @ 7168: { X4[64*28] float4 (28672B) | w1T[128*66]+h[28*64]+b1w2[128] (41472B) }
#define OFF_SL2  (KPB * NBINS)                 // 3584
#define OFF_U    (2 * KPB * NBINS)             // 7168
#define OFF_H    (OFF_U + 128 * 66)            // 15616
#define OFF_B1W2 (OFF_H + KPB * MLPH)          // 17408
#define SMEM_BYTES ((OFF_B1W2 + 2 * MLPH) * 4) // 70144

__global__ __launch_bounds__(TPB, 2)
void key_pruning_main(const float2* __restrict__ K2,
                      const int*    __restrict__ pos,
                      const float*  __restrict__ bias,
                      const float*  __restrict__ W1,      // [64][128]
                      const float*  __restrict__ b1,
                      const float*  __restrict__ W2,
                      const float*  __restrict__ b2,
                      const float*  __restrict__ araw,
                      float*        __restrict__ out,
                      int n) {
    extern __shared__ float sm[];
    float4* X4 = (float4*)(sm + OFF_U);

    const int tid  = threadIdx.x;
    const int warp = tid >> 5;
    const int lane = tid & 31;
    const int key0 = blockIdx.x * KPB;

    // ---- Phase 1: compact features {mag, 2*c1, x, y} ----
    for (int i = tid; i < KPB * NFREQ; i += TPB) {
        int kk = i / NFREQ;
        int f  = i & (NFREQ - 1);
        int key = key0 + kk; if (key >= n) key = n - 1;
        float2 v = K2[key * NFREQ + f];
        float r2 = fmaf(v.x, v.x, v.y * v.y);
        r2 = fmaxf(r2, 1e-30f);
        float rinv = rsqrtf(r2);
        float mag = r2 * rinv;
        float c1x2 = 2.f * v.x * rinv;
        X4[f * KPB + kk] = make_float4(mag, c1x2, v.x, v.y);
    }
    __syncthreads();

    // ---- Phase 2: logits GEMM. warp = 28 keys x 64 bins x 16 f.
    //      Thread: 7 keys x 8 bins (4 packed pairs/key). HW prefetch dist 2. ----
    const int fq    = warp >> 1;              // f quarter: [16*fq, 16*fq+16)
    const int bh    = warp & 1;               // bin half
    const int kq    = lane >> 3;
    const int b0    = bh * 64 + (lane & 7) * 8;  // thread bins b0..b0+7
    const int kbase = kq * JKEYS;
    const int fbase = fq * 16;

    ull acc[4 * JKEYS];
    #pragma unroll
    for (int i = 0; i < 4 * JKEYS; i++) acc[i] = 0ull;

    const float* gC = (const float*)g_C4;
    const float* Cf = gC + fbase * 7 * NBINS + b0;

    for (int fo = 0; fo < 16; fo++) {
        int f = fbase + fo;
        // prefetch f+2's C rows into L1 (padded table keeps this in-bounds)
        {
            const float* pp = Cf + 14 * NBINS;
            #pragma unroll
            for (int c = 0; c < 7; c++) pref_l1(pp + c * NBINS);
        }
        ulonglong2 Cc[14];
        #pragma unroll
        for (int c = 0; c < 7; c++) {
            Cc[2 * c]     = *(const ulonglong2*)(Cf + c * NBINS);
            Cc[2 * c + 1] = *(const ulonglong2*)(Cf + c * NBINS + 4);
        }
        Cf += 7 * NBINS;
        #pragma unroll
        for (int j = 0; j < JKEYS; j++) {
            float4 x = X4[f * KPB + kbase + j];
            float xs0 = x.x;                        // m
            float c1x2 = x.y;                       // 2*cos1
            float xs1 = x.z;                        // m*cos1
            float xs2 = x.w;                        // m*sin1
            float xs3 = fmaf(c1x2, xs1, -xs0);      // m*cos2
            float xs4 = c1x2 * xs2;                 // m*sin2
            float xs5 = fmaf(c1x2, xs3, -xs1);      // m*cos3
            float xs6 = fmaf(c1x2, xs4, -xs2);      // m*sin3
            ull* a = &acc[4 * j];
            #define STEP(c, v) { ull d = dup2(v); \
                fma2(a[0], d, Cc[2*(c)].x);  fma2(a[1], d, Cc[2*(c)].y); \
                fma2(a[2], d, Cc[2*(c)+1].x); fma2(a[3], d, Cc[2*(c)+1].y); }
            STEP(0, xs0) STEP(1, xs1) STEP(2, xs2) STEP(3, xs3)
            STEP(4, xs4) STEP(5, xs5) STEP(6, xs6)
            #undef STEP
        }
    }

    // ---- partial writes: fq0 -> sl, fq2 -> sl2 (disjoint; X4 still live for others) ----
    if (fq == 0 || fq == 2) {
        float* dst = (fq == 0) ? sm : (sm + OFF_SL2);
        #pragma unroll
        for (int j = 0; j < JKEYS; j++) {
            float2 p0 = unpack2(acc[4 * j]);
            float2 p1 = unpack2(acc[4 * j + 1]);
            float2 p2 = unpack2(acc[4 * j + 2]);
            float2 p3 = unpack2(acc[4 * j + 3]);
            *(float4*)&dst[(kbase + j) * NBINS + b0]     = make_float4(p0.x, p0.y, p1.x, p1.y);
            *(float4*)&dst[(kbase + j) * NBINS + b0 + 4] = make_float4(p2.x, p2.y, p3.x, p3.y);
        }
    }
    __syncthreads();   // all phase-2 done; X4 dead

    if (fq == 1 || fq == 3) {
        float* dst = (fq == 1) ? sm : (sm + OFF_SL2);
        #pragma unroll
        for (int j = 0; j < JKEYS; j++) {
            float2 p0 = unpack2(acc[4 * j]);
            float2 p1 = unpack2(acc[4 * j + 1]);
            float2 p2 = unpack2(acc[4 * j + 2]);
            float2 p3 = unpack2(acc[4 * j + 3]);
            float4 c0 = *(float4*)&dst[(kbase + j) * NBINS + b0];
            float4 c1 = *(float4*)&dst[(kbase + j) * NBINS + b0 + 4];
            c0.x += p0.x; c0.y += p0.y; c0.z += p1.x; c0.w += p1.y;
            c1.x += p2.x; c1.y += p2.y; c1.z += p3.x; c1.w += p3.y;
            *(float4*)&dst[(kbase + j) * NBINS + b0]     = c0;
            *(float4*)&dst[(kbase + j) * NBINS + b0 + 4] = c1;
        }
    } else {
        // ---- Phase 3 (overlapped): warps 0,1,4,5 stage transposed W1 + b1w2 ----
        int ci = ((warp & 1) | ((warp >> 2) << 1)) * 32 + lane;  // 0..127
        for (int i = ci; i < MLPH * NBINS; i += 128) {
            int h = i >> 7;
            int k = i & 127;
            sm[OFF_U + k * 66 + h] = W1[i];
        }
        if (ci < MLPH) {
            sm[OFF_B1W2 + ci]        = b1[ci];
            sm[OFF_B1W2 + MLPH + ci] = W2[ci];
        }
    }
    __syncthreads();

    // ---- merge: sl = sl + sl2 + bias ----
    {
        float4* sl4  = (float4*)sm;
        float4* sl24 = (float4*)(sm + OFF_SL2);
        const float4* bias4 = (const float4*)bias;
        for (int i = tid; i < KPB * NBINS / 4; i += TPB) {
            float4 a = sl4[i];
            float4 b = sl24[i];
            float4 bb = __ldg(&bias4[i & 31]);
            a.x += b.x + bb.x; a.y += b.y + bb.y;
            a.z += b.z + bb.z; a.w += b.w + bb.w;
            sl4[i] = a;
        }
    }
    __syncthreads();

    // ---- Phase 4: MLP layer 1, 256 threads: 7 keys x 1 hidden, fma2 over k-pairs ----
    {
        int hb  = tid & 63;            // hidden unit
        int pkq = tid >> 6;            // key quarter
        ull am[JKEYS];
        #pragma unroll
        for (int j = 0; j < JKEYS; j++) am[j] = 0ull;
        #pragma unroll 4
        for (int k2 = 0; k2 < 64; k2++) {
            int k = 2 * k2;
            float w0 = sm[OFF_U + k * 66 + hb];
            float w1 = sm[OFF_U + (k + 1) * 66 + hb];
            ull wp = pack2(w0, w1);
            #pragma unroll
            for (int j = 0; j < JKEYS; j++) {
                ull lp = *(const ull*)&sm[(pkq * JKEYS + j) * NBINS + k];
                fma2(am[j], lp, wp);
            }
        }
        float bb = sm[OFF_B1W2 + hb];
        float w2 = sm[OFF_B1W2 + MLPH + hb];
        #pragma unroll
        for (int j = 0; j < JKEYS; j++) {
            float2 p = unpack2(am[j]);
            float h = fmaxf(p.x + p.y + bb, 0.f) * w2;
            sm[OFF_H + (pkq * JKEYS + j) * MLPH + hb] = h;
        }
    }
    __syncthreads();

    // ---- Phase 5: reduce, position weight, sigmoid ----
    if (tid < KPB && (key0 + tid) < n) {
        float s = b2[0];
        const float4* hp = (const float4*)&sm[OFF_H + tid * MLPH];
        float s1 = 0.f, s2 = 0.f, s3 = 0.f;
        #pragma unroll
        for (int j = 0; j < MLPH / 4; j++) {
            float4 v = hp[j];
            s += v.x; s1 += v.y; s2 += v.z; s3 += v.w;
        }
        s = (s + s1) + (s2 + s3);

        int p = pos[key0 + tid];
        float lp = log10f(fmaxf((float)p, 1.0f));
        float a0 = log1pf(expf(araw[0]));
        float a1 = log1pf(expf(araw[1]));
        float a2 = log1pf(expf(araw[2]));
        float w;
        if (lp < 3.f)      w = a0;
        else if (lp < 4.f) w = a0 + (a1 - a0) * (lp - 3.f);
        else if (lp < 5.f) w = a1 + (a2 - a1) * (lp - 4.f);
        else               w = a2;

        float z = s * w;
        out[key0 + tid] = 1.f / (1.f + expf(-z));
    }
}

extern "C" void kernel_launch(void* const* d_in, const int* in_sizes, int n_in,
                              void* d_out, int out_size) {
    const float* K      = (const float*)d_in[0];
    const int*   pos    = (const int*)  d_in[1];
    const float* ra     = (const float*)d_in[2];
    const float* mu     = (const float*)d_in[3];
    const float* kappa  = (const float*)d_in[4];
    const float* weight = (const float*)d_in[5];
    const float* bias   = (const float*)d_in[6];
    const float* W1     = (const float*)d_in[7];
    const float* b1     = (const float*)d_in[8];
    const float* W2     = (const float*)d_in[9];
    const float* b2     = (const float*)d_in[10];
    const float* araw   = (const float*)d_in[11];

    int n = in_sizes[1];   // number of keys

    static int smem_set = 0;
    if (!smem_set) {
        cudaFuncSetAttribute(key_pruning_main,
                             cudaFuncAttributeMaxDynamicSharedMemorySize, SMEM_BYTES);
        smem_set = 1;
    }

    precompute_fourier<<<(NBINS * NFREQ + 127) / 128, 128>>>(mu, kappa, weight, ra);

    int grid = (n + KPB - 1) / KPB;
    key_pruning_main<<<grid, TPB, SMEM_BYTES>>>((const float2*)K, pos, bias, W1, b1, W2, b2, araw,
                                                (float*)d_out, n);
}

// round 15
// speedup vs baseline: 1.7485x; 1.7485x over previous
#include <cuda_runtime.h>
#include <cuda_bf16.h>
#include <math.h>

#define NBINS 128
#define NFREQ 64
#define NKERN 3
#define MLPH  64
#define KPB   28   // keys per block -> grid 293; 2 blocks/SM
#define TPB   256

typedef unsigned long long ull;

// Planar coefficient table: g_C[f][coord][bin], coord 0..6 =
//   [A0, A1c, A1s, A2c, A2s, A3c, A3s]
// +2 f of zero padding: distance-2 prefetch + distance-2 double-buffer reads stay in-bounds.
__device__ float4 g_C4[(NFREQ + 2) * 7 * NBINS / 4];

__device__ __forceinline__ void fma2(ull& acc, ull a, ull b) {
    asm("fma.rn.f32x2 %0, %1, %2, %0;" : "+l"(acc) : "l"(a), "l"(b));
}
__device__ __forceinline__ ull dup2(float v) {
    ull r;
    asm("mov.b64 %0, {%1, %1};" : "=l"(r) : "f"(v));
    return r;
}
__device__ __forceinline__ float2 unpack2(ull v) {
    float2 r;
    asm("mov.b64 {%0, %1}, %2;" : "=f"(r.x), "=f"(r.y) : "l"(v));
    return r;
}
__device__ __forceinline__ void pref_l1(const void* p) {
    asm volatile("prefetch.global.L1 [%0];" :: "l"(p));
}

// I_k(kappa) via Horner series in h2 = (kappa/2)^2, no divisions.
__global__ void precompute_fourier(const float* __restrict__ mu,
                                   const float* __restrict__ kappa,
                                   const float* __restrict__ weight,
                                   const float* __restrict__ ref_angles) {
    int idx = blockIdx.x * blockDim.x + threadIdx.x;
    if (idx >= NBINS * NFREQ) return;
    int b = idx / NFREQ;
    int f = idx % NFREQ;
    float C[7];
    #pragma unroll
    for (int i = 0; i < 7; i++) C[i] = 0.f;

    #pragma unroll
    for (int m = 0; m < NKERN; m++) {
        int off = (b * NFREQ + f) * NKERN + m;
        float kp = kappa[off];
        float w  = weight[off];
        float me = mu[off] + ref_angles[f];
        float h  = 0.5f * kp;
        float h2 = h * h;
        float ek = __expf(-kp);
        float P0 = fmaf(h2, fmaf(h2, fmaf(h2, fmaf(h2, fmaf(h2, fmaf(h2,
                    1.9290123e-6f, 6.9444444e-5f), 1.7361111e-3f), 2.7777778e-2f),
                    0.25f), 1.0f), 1.0f);
        float P1 = fmaf(h2, fmaf(h2, fmaf(h2, fmaf(h2, fmaf(h2, fmaf(h2,
                    2.7557319e-7f, 1.1574074e-5f), 3.4722222e-4f), 6.9444444e-3f),
                    8.3333333e-2f), 0.5f), 1.0f);
        float P2 = fmaf(h2, fmaf(h2, fmaf(h2, fmaf(h2, fmaf(h2, fmaf(h2,
                    3.4446e-8f, 1.6534392e-6f), 5.7870370e-5f), 1.3888889e-3f),
                    2.0833333e-2f), 1.6666667e-1f), 0.5f);
        float P3 = fmaf(h2, fmaf(h2, fmaf(h2, fmaf(h2, fmaf(h2, fmaf(h2,
                    3.83e-9f, 2.0667e-7f), 8.2671958e-6f), 2.3148148e-4f),
                    4.1666667e-3f), 4.1666667e-2f), 1.6666667e-1f);
        float I0 = P0;
        float I1 = h * P1;
        float I2 = h2 * P2;
        float I3 = h2 * h * P3;

        float cm, sm;
        __sincosf(me, &sm, &cm);
        float wek = w * ek;
        C[0] += wek * I0;
        float g1 = 2.f * wek * I1;
        C[1] += g1 * cm;
        C[2] += g1 * sm;
        float c2 = cm * cm - sm * sm;
        float s2 = 2.f * cm * sm;
        float g2 = 2.f * wek * I2;
        C[3] += g2 * c2;
        C[4] += g2 * s2;
        float c3 = c2 * cm - s2 * sm;
        float s3 = s2 * cm + c2 * sm;
        float g3 = 2.f * wek * I3;
        C[5] += g3 * c3;
        C[6] += g3 * s3;
    }
    float* gC = (float*)g_C4;
    #pragma unroll
    for (int c = 0; c < 7; c++)
        gC[(f * 7 + c) * NBINS + b] = C[c];
}

// dynamic smem (floats):
//   sl[28*128] @ 0  | union { X4[64*28] float4 | w1T[128*66]+h[28*64]+b1w2[128] }
#define OFF_U    (KPB * NBINS)                 // 3584
#define OFF_H    (OFF_U + 128 * 66)
#define OFF_B1W2 (OFF_H + KPB * MLPH)
#define SMEM_BYTES ((OFF_B1W2 + 2 * MLPH) * 4) // 55808

__global__ __launch_bounds__(TPB, 2)
void key_pruning_main(const float2* __restrict__ K2,
                      const int*    __restrict__ pos,
                      const float*  __restrict__ bias,
                      const float*  __restrict__ W1,      // [64][128]
                      const float*  __restrict__ b1,
                      const float*  __restrict__ W2,
                      const float*  __restrict__ b2,
                      const float*  __restrict__ araw,
                      float*        __restrict__ out,
                      int n) {
    extern __shared__ float sm[];
    float4* X4 = (float4*)(sm + OFF_U);

    const int tid  = threadIdx.x;
    const int warp = tid >> 5;
    const int lane = tid & 31;
    const int key0 = blockIdx.x * KPB;

    // ---- Phase 1: compact features {mag, 2*c1, x, y} ----
    for (int i = tid; i < KPB * NFREQ; i += TPB) {
        int kk = i / NFREQ;
        int f  = i & (NFREQ - 1);
        int key = key0 + kk; if (key >= n) key = n - 1;
        float2 v = K2[key * NFREQ + f];
        float r2 = fmaf(v.x, v.x, v.y * v.y);
        r2 = fmaxf(r2, 1e-30f);
        float rinv = rsqrtf(r2);
        float mag = r2 * rinv;
        float c1x2 = 2.f * v.x * rinv;
        X4[f * KPB + kk] = make_float4(mag, c1x2, v.x, v.y);
    }
    __syncthreads();

    // ---- Phase 2: logits GEMM with double-buffered C + distance-2 L1 prefetch. ----
    const int fbase = (warp >= 4) ? 32 : 0;
    const int wb    = (warp & 3) * 32;
    const int kq    = lane >> 3;
    const int b0    = wb + (lane & 7) * 4;   // thread bins b0..b0+3
    const int kbase = kq * 7;

    ull acc[14];
    #pragma unroll
    for (int i = 0; i < 14; i++) acc[i] = 0ull;

    const float* gC = (const float*)g_C4;
    const float* Cf = gC + fbase * 7 * NBINS + b0;

    ulonglong2 CA[7], CB[7];
    #pragma unroll
    for (int c = 0; c < 7; c++)
        CA[c] = *(const ulonglong2*)(Cf + c * NBINS);
    // warm L1 for f+1 (loaded as CB shortly) and f+2
    {
        const float* p1 = Cf + 7 * NBINS;
        const float* p2 = Cf + 14 * NBINS;
        #pragma unroll
        for (int c = 0; c < 7; c++) { pref_l1(p1 + c * NBINS); pref_l1(p2 + c * NBINS); }
    }

    #define COMPUTE(BUF, FIDX) do {                                           \
        const int _f = (FIDX);                                                \
        _Pragma("unroll")                                                     \
        for (int j = 0; j < 7; j++) {                                         \
            float4 x = X4[_f * KPB + kbase + j];                              \
            float xs0 = x.x;                                                  \
            float c1x2 = x.y;                                                 \
            float xs1 = x.z;                                                  \
            float xs2 = x.w;                                                  \
            float xs3 = fmaf(c1x2, xs1, -xs0);                                \
            float xs4 = c1x2 * xs2;                                           \
            float xs5 = fmaf(c1x2, xs3, -xs1);                                \
            float xs6 = fmaf(c1x2, xs4, -xs2);                                \
            ull* a = &acc[2 * j];                                             \
            { ull d = dup2(xs0); fma2(a[0], d, BUF[0].x); fma2(a[1], d, BUF[0].y); } \
            { ull d = dup2(xs1); fma2(a[0], d, BUF[1].x); fma2(a[1], d, BUF[1].y); } \
            { ull d = dup2(xs2); fma2(a[0], d, BUF[2].x); fma2(a[1], d, BUF[2].y); } \
            { ull d = dup2(xs3); fma2(a[0], d, BUF[3].x); fma2(a[1], d, BUF[3].y); } \
            { ull d = dup2(xs4); fma2(a[0], d, BUF[4].x); fma2(a[1], d, BUF[4].y); } \
            { ull d = dup2(xs5); fma2(a[0], d, BUF[5].x); fma2(a[1], d, BUF[5].y); } \
            { ull d = dup2(xs6); fma2(a[0], d, BUF[6].x); fma2(a[1], d, BUF[6].y); } \
        }                                                                     \
    } while (0)

    for (int fo = 0; fo < 32; fo += 2) {
        const float* Cn1 = Cf + 7 * NBINS;     // f+1
        #pragma unroll
        for (int c = 0; c < 7; c++)
            CB[c] = *(const ulonglong2*)(Cn1 + c * NBINS);
        {   // prefetch f+3 into L1 (padded table: safe at end)
            const float* pp = Cf + 21 * NBINS;
            #pragma unroll
            for (int c = 0; c < 7; c++) pref_l1(pp + c * NBINS);
        }
        COMPUTE(CA, fbase + fo);

        const float* Cn2 = Cf + 14 * NBINS;    // f+2
        #pragma unroll
        for (int c = 0; c < 7; c++)
            CA[c] = *(const ulonglong2*)(Cn2 + c * NBINS);
        {   // prefetch f+4
            const float* pp = Cf + 28 * NBINS;
            #pragma unroll
            for (int c = 0; c < 7; c++) pref_l1(pp + c * NBINS);
        }
        COMPUTE(CB, fbase + fo + 1);

        Cf = Cn2;
    }
    #undef COMPUTE

    // f-split reduction into sl (low-f warps write with bias; high-f warps add)
    float4 bias4 = *(const float4*)&bias[b0];
    if (warp < 4) {
        #pragma unroll
        for (int j = 0; j < 7; j++) {
            float2 p0 = unpack2(acc[2 * j]);
            float2 p1 = unpack2(acc[2 * j + 1]);
            float4 o = make_float4(p0.x + bias4.x, p0.y + bias4.y,
                                   p1.x + bias4.z, p1.y + bias4.w);
            *(float4*)&sm[(kbase + j) * NBINS + b0] = o;
        }
    }
    __syncthreads();
    if (warp >= 4) {
        #pragma unroll
        for (int j = 0; j < 7; j++) {
            float2 p0 = unpack2(acc[2 * j]);
            float2 p1 = unpack2(acc[2 * j + 1]);
            float4 cur = *(float4*)&sm[(kbase + j) * NBINS + b0];
            cur.x += p0.x; cur.y += p0.y; cur.z += p1.x; cur.w += p1.y;
            *(float4*)&sm[(kbase + j) * NBINS + b0] = cur;
        }
    } else {
        // ---- Phase 3 (overlapped): stage transposed W1 [k][h], stride 66 ----
        for (int i = tid; i < MLPH * NBINS; i += 128) {
            int h = i >> 7;
            int k = i & 127;
            sm[OFF_U + k * 66 + h] = W1[i];
        }
        if (tid < MLPH) {
            sm[OFF_B1W2 + tid]        = b1[tid];
            sm[OFF_B1W2 + MLPH + tid] = W2[tid];
        }
    }
    __syncthreads();

    // ---- Phase 4: MLP layer 1 on 128 threads: 7 keys x 2 hidden per thread ----
    if (tid < 128) {
        int pkq = tid >> 5;            // key quarter (uniform per warp)
        int hb  = (tid & 31) * 2;      // hidden pair
        float a[7][2];
        #pragma unroll
        for (int j = 0; j < 7; j++) { a[j][0] = 0.f; a[j][1] = 0.f; }
        #pragma unroll 4
        for (int k = 0; k < NBINS; k++) {
            float2 w = *(const float2*)&sm[OFF_U + k * 66 + hb];
            #pragma unroll
            for (int j = 0; j < 7; j++) {
                float l = sm[(pkq * 7 + j) * NBINS + k];
                a[j][0] = fmaf(l, w.x, a[j][0]);
                a[j][1] = fmaf(l, w.y, a[j][1]);
            }
        }
        float bb0 = sm[OFF_B1W2 + hb],        bb1 = sm[OFF_B1W2 + hb + 1];
        float w20 = sm[OFF_B1W2 + MLPH + hb], w21 = sm[OFF_B1W2 + MLPH + hb + 1];
        #pragma unroll
        for (int j = 0; j < 7; j++) {
            float h0 = fmaxf(a[j][0] + bb0, 0.f) * w20;
            float h1 = fmaxf(a[j][1] + bb1, 0.f) * w21;
            *(float2*)&sm[OFF_H + (pkq * 7 + j) * MLPH + hb] = make_float2(h0, h1);
        }
    }
    __syncthreads();

    // ---- Phase 5: reduce, position weight, sigmoid ----
    if (tid < KPB && (key0 + tid) < n) {
        float s = b2[0];
        const float4* hp = (const float4*)&sm[OFF_H + tid * MLPH];
        float s1 = 0.f, s2 = 0.f, s3 = 0.f;
        #pragma unroll
        for (int j = 0; j < MLPH / 4; j++) {
            float4 v = hp[j];
            s += v.x; s1 += v.y; s2 += v.z; s3 += v.w;
        }
        s = (s + s1) + (s2 + s3);

        int p = pos[key0 + tid];
        float lp = log10f(fmaxf((float)p, 1.0f));
        float a0 = log1pf(expf(araw[0]));
        float a1 = log1pf(expf(araw[1]));
        float a2 = log1pf(expf(araw[2]));
        float w;
        if (lp < 3.f)      w = a0;
        else if (lp < 4.f) w = a0 + (a1 - a0) * (lp - 3.f);
        else if (lp < 5.f) w = a1 + (a2 - a1) * (lp - 4.f);
        else               w = a2;

        float z = s * w;
        out[key0 + tid] = 1.f / (1.f + expf(-z));
    }
}

extern "C" void kernel_launch(void* const* d_in, const int* in_sizes, int n_in,
                              void* d_out, int out_size) {
    const float* K      = (const float*)d_in[0];
    const int*   pos    = (const int*)  d_in[1];
    const float* ra     = (const float*)d_in[2];
    const float* mu     = (const float*)d_in[3];
    const float* kappa  = (const float*)d_in[4];
    const float* weight = (const float*)d_in[5];
    const float* bias   = (const float*)d_in[6];
    const float* W1     = (const float*)d_in[7];
    const float* b1     = (const float*)d_in[8];
    const float* W2     = (const float*)d_in[9];
    const float* b2     = (const float*)d_in[10];
    const float* araw   = (const float*)d_in[11];

    int n = in_sizes[1];   // number of keys

    static int smem_set = 0;
    if (!smem_set) {
        cudaFuncSetAttribute(key_pruning_main,
                             cudaFuncAttributeMaxDynamicSharedMemorySize, SMEM_BYTES);
        smem_set = 1;
    }

    precompute_fourier<<<(NBINS * NFREQ + 127) / 128, 128>>>(mu, kappa, weight, ra);

    int grid = (n + KPB - 1) / KPB;
    key_pruning_main<<<grid, TPB, SMEM_BYTES>>>((const float2*)K, pos, bias, W1, b1, W2, b2, araw,
                                                (float*)d_out, n);
}

// round 16
// speedup vs baseline: 1.7755x; 1.0154x over previous
#include <cuda_runtime.h>
#include <cuda_bf16.h>
#include <math.h>

#define NBINS 128
#define NFREQ 64
#define NKERN 3
#define MLPH  64
#define KPB   28   // keys per block -> grid 293; 2 blocks/SM
#define TPB   256

typedef unsigned long long ull;

// Planar coefficient table: g_C[f][coord][bin], coord 0..6 =
//   [A0, A1c, A1s, A2c, A2s, A3c, A3s]
// +1 f of zero padding so the double-buffer can read one f past the end.
__device__ float4 g_C4[(NFREQ + 1) * 7 * NBINS / 4];

__device__ __forceinline__ void fma2(ull& acc, ull a, ull b) {
    asm("fma.rn.f32x2 %0, %1, %2, %0;" : "+l"(acc) : "l"(a), "l"(b));
}
__device__ __forceinline__ ull dup2(float v) {
    ull r;
    asm("mov.b64 %0, {%1, %1};" : "=l"(r) : "f"(v));
    return r;
}
__device__ __forceinline__ float2 unpack2(ull v) {
    float2 r;
    asm("mov.b64 {%0, %1}, %2;" : "=f"(r.x), "=f"(r.y) : "l"(v));
    return r;
}
// 16B load with evict-last L1 policy: C lines are shared with the co-resident
// block on the same SM; keep them L1-resident.
__device__ __forceinline__ ulonglong2 ldg_el(const float* p) {
    ulonglong2 v;
    asm("ld.global.nc.L1::evict_last.v2.u64 {%0, %1}, [%2];"
        : "=l"(v.x), "=l"(v.y) : "l"(p));
    return v;
}

// Fast precompute: one (b,f,m) per thread in 4-lane groups (m=3 idle),
// butterfly-shuffle combine, lane m==0 writes the 7 coefficients.
__global__ void precompute_fourier(const float* __restrict__ mu,
                                   const float* __restrict__ kappa,
                                   const float* __restrict__ weight,
                                   const float* __restrict__ ref_angles) {
    int t = blockIdx.x * blockDim.x + threadIdx.x;
    int pair = t >> 2;          // (b,f) index
    int m    = t & 3;           // kernel index; m==3 idle
    if (pair >= NBINS * NFREQ) return;
    int b = pair / NFREQ;
    int f = pair % NFREQ;

    float C[7];
    #pragma unroll
    for (int i = 0; i < 7; i++) C[i] = 0.f;

    if (m < NKERN) {
        int off = (b * NFREQ + f) * NKERN + m;
        float kp = kappa[off];
        float w  = weight[off];
        float me = mu[off] + ref_angles[f];
        float h  = 0.5f * kp;
        float h2 = h * h;
        float ek = __expf(-kp);
        float P0 = fmaf(h2, fmaf(h2, fmaf(h2, fmaf(h2, fmaf(h2, fmaf(h2,
                    1.9290123e-6f, 6.9444444e-5f), 1.7361111e-3f), 2.7777778e-2f),
                    0.25f), 1.0f), 1.0f);
        float P1 = fmaf(h2, fmaf(h2, fmaf(h2, fmaf(h2, fmaf(h2, fmaf(h2,
                    2.7557319e-7f, 1.1574074e-5f), 3.4722222e-4f), 6.9444444e-3f),
                    8.3333333e-2f), 0.5f), 1.0f);
        float P2 = fmaf(h2, fmaf(h2, fmaf(h2, fmaf(h2, fmaf(h2, fmaf(h2,
                    3.4446e-8f, 1.6534392e-6f), 5.7870370e-5f), 1.3888889e-3f),
                    2.0833333e-2f), 1.6666667e-1f), 0.5f);
        float P3 = fmaf(h2, fmaf(h2, fmaf(h2, fmaf(h2, fmaf(h2, fmaf(h2,
                    3.83e-9f, 2.0667e-7f), 8.2671958e-6f), 2.3148148e-4f),
                    4.1666667e-3f), 4.1666667e-2f), 1.6666667e-1f);
        float I0 = P0;
        float I1 = h * P1;
        float I2 = h2 * P2;
        float I3 = h2 * h * P3;

        float cm, sm;
        __sincosf(me, &sm, &cm);
        float wek = w * ek;
        C[0] = wek * I0;
        float g1 = 2.f * wek * I1;
        C[1] = g1 * cm;
        C[2] = g1 * sm;
        float c2 = cm * cm - sm * sm;
        float s2 = 2.f * cm * sm;
        float g2 = 2.f * wek * I2;
        C[3] = g2 * c2;
        C[4] = g2 * s2;
        float c3 = c2 * cm - s2 * sm;
        float s3 = s2 * cm + c2 * sm;
        float g3 = 2.f * wek * I3;
        C[5] = g3 * c3;
        C[6] = g3 * s3;
    }
    // combine m=0..3 within the 4-lane group
    #pragma unroll
    for (int c = 0; c < 7; c++) {
        C[c] += __shfl_xor_sync(0xFFFFFFFF, C[c], 1);
        C[c] += __shfl_xor_sync(0xFFFFFFFF, C[c], 2);
    }
    if (m == 0) {
        float* gC = (float*)g_C4;
        #pragma unroll
        for (int c = 0; c < 7; c++)
            gC[(f * 7 + c) * NBINS + b] = C[c];
    }
}

// dynamic smem (floats):
//   sl[28*128] @ 0  | union { X4[64*28] float4 | w1T[128*66]+h[28*64]+b1w2[128] }
#define OFF_U    (KPB * NBINS)                 // 3584
#define OFF_H    (OFF_U + 128 * 66)
#define OFF_B1W2 (OFF_H + KPB * MLPH)
#define SMEM_BYTES ((OFF_B1W2 + 2 * MLPH) * 4) // 55808

__global__ __launch_bounds__(TPB, 2)
void key_pruning_main(const float2* __restrict__ K2,
                      const int*    __restrict__ pos,
                      const float*  __restrict__ bias,
                      const float*  __restrict__ W1,      // [64][128]
                      const float*  __restrict__ b1,
                      const float*  __restrict__ W2,
                      const float*  __restrict__ b2,
                      const float*  __restrict__ araw,
                      float*        __restrict__ out,
                      int n) {
    extern __shared__ float sm[];
    float4* X4 = (float4*)(sm + OFF_U);

    const int tid  = threadIdx.x;
    const int warp = tid >> 5;
    const int lane = tid & 31;
    const int key0 = blockIdx.x * KPB;

    // ---- Phase 1: compact features {mag, 2*c1, x, y} ----
    for (int i = tid; i < KPB * NFREQ; i += TPB) {
        int kk = i / NFREQ;
        int f  = i & (NFREQ - 1);
        int key = key0 + kk; if (key >= n) key = n - 1;
        float2 v = K2[key * NFREQ + f];
        float r2 = fmaf(v.x, v.x, v.y * v.y);
        r2 = fmaxf(r2, 1e-30f);
        float rinv = rsqrtf(r2);
        float mag = r2 * rinv;
        float c1x2 = 2.f * v.x * rinv;
        X4[f * KPB + kk] = make_float4(mag, c1x2, v.x, v.y);
    }
    __syncthreads();

    // ---- Phase 2: logits GEMM with double-buffered C (evict_last loads). ----
    const int fbase = (warp >= 4) ? 32 : 0;
    const int wb    = (warp & 3) * 32;
    const int kq    = lane >> 3;
    const int b0    = wb + (lane & 7) * 4;   // thread bins b0..b0+3
    const int kbase = kq * 7;

    ull acc[14];
    #pragma unroll
    for (int i = 0; i < 14; i++) acc[i] = 0ull;

    const float* gC = (const float*)g_C4;
    const float* Cf = gC + fbase * 7 * NBINS + b0;

    ulonglong2 CA[7], CB[7];
    #pragma unroll
    for (int c = 0; c < 7; c++)
        CA[c] = ldg_el(Cf + c * NBINS);

    #define COMPUTE(BUF, FIDX) do {                                           \
        const int _f = (FIDX);                                                \
        _Pragma("unroll")                                                     \
        for (int j = 0; j < 7; j++) {                                         \
            float4 x = X4[_f * KPB + kbase + j];                              \
            float xs0 = x.x;                                                  \
            float c1x2 = x.y;                                                 \
            float xs1 = x.z;                                                  \
            float xs2 = x.w;                                                  \
            float xs3 = fmaf(c1x2, xs1, -xs0);                                \
            float xs4 = c1x2 * xs2;                                           \
            float xs5 = fmaf(c1x2, xs3, -xs1);                                \
            float xs6 = fmaf(c1x2, xs4, -xs2);                                \
            ull* a = &acc[2 * j];                                             \
            { ull d = dup2(xs0); fma2(a[0], d, BUF[0].x); fma2(a[1], d, BUF[0].y); } \
            { ull d = dup2(xs1); fma2(a[0], d, BUF[1].x); fma2(a[1], d, BUF[1].y); } \
            { ull d = dup2(xs2); fma2(a[0], d, BUF[2].x); fma2(a[1], d, BUF[2].y); } \
            { ull d = dup2(xs3); fma2(a[0], d, BUF[3].x); fma2(a[1], d, BUF[3].y); } \
            { ull d = dup2(xs4); fma2(a[0], d, BUF[4].x); fma2(a[1], d, BUF[4].y); } \
            { ull d = dup2(xs5); fma2(a[0], d, BUF[5].x); fma2(a[1], d, BUF[5].y); } \
            { ull d = dup2(xs6); fma2(a[0], d, BUF[6].x); fma2(a[1], d, BUF[6].y); } \
        }                                                                     \
    } while (0)

    for (int fo = 0; fo < 32; fo += 2) {
        const float* Cn1 = Cf + 7 * NBINS;     // f+1
        #pragma unroll
        for (int c = 0; c < 7; c++)
            CB[c] = ldg_el(Cn1 + c * NBINS);
        COMPUTE(CA, fbase + fo);

        const float* Cn2 = Cf + 14 * NBINS;    // f+2 (padded table: safe at end)
        #pragma unroll
        for (int c = 0; c < 7; c++)
            CA[c] = ldg_el(Cn2 + c * NBINS);
        COMPUTE(CB, fbase + fo + 1);

        Cf = Cn2;
    }
    #undef COMPUTE

    // f-split reduction into sl (low-f warps write with bias; high-f warps add)
    float4 bias4 = *(const float4*)&bias[b0];
    if (warp < 4) {
        #pragma unroll
        for (int j = 0; j < 7; j++) {
            float2 p0 = unpack2(acc[2 * j]);
            float2 p1 = unpack2(acc[2 * j + 1]);
            float4 o = make_float4(p0.x + bias4.x, p0.y + bias4.y,
                                   p1.x + bias4.z, p1.y + bias4.w);
            *(float4*)&sm[(kbase + j) * NBINS + b0] = o;
        }
    }
    __syncthreads();
    if (warp >= 4) {
        #pragma unroll
        for (int j = 0; j < 7; j++) {
            float2 p0 = unpack2(acc[2 * j]);
            float2 p1 = unpack2(acc[2 * j + 1]);
            float4 cur = *(float4*)&sm[(kbase + j) * NBINS + b0];
            cur.x += p0.x; cur.y += p0.y; cur.z += p1.x; cur.w += p1.y;
            *(float4*)&sm[(kbase + j) * NBINS + b0] = cur;
        }
    } else {
        // ---- Phase 3 (overlapped): stage transposed W1 [k][h], stride 66 ----
        for (int i = tid; i < MLPH * NBINS; i += 128) {
            int h = i >> 7;
            int k = i & 127;
            sm[OFF_U + k * 66 + h] = W1[i];
        }
        if (tid < MLPH) {
            sm[OFF_B1W2 + tid]        = b1[tid];
            sm[OFF_B1W2 + MLPH + tid] = W2[tid];
        }
    }
    __syncthreads();

    // ---- Phase 4: MLP layer 1 on 128 threads: 7 keys x 2 hidden per thread ----
    if (tid < 128) {
        int pkq = tid >> 5;            // key quarter (uniform per warp)
        int hb  = (tid & 31) * 2;      // hidden pair
        float a[7][2];
        #pragma unroll
        for (int j = 0; j < 7; j++) { a[j][0] = 0.f; a[j][1] = 0.f; }
        #pragma unroll 4
        for (int k = 0; k < NBINS; k++) {
            float2 w = *(const float2*)&sm[OFF_U + k * 66 + hb];
            #pragma unroll
            for (int j = 0; j < 7; j++) {
                float l = sm[(pkq * 7 + j) * NBINS + k];
                a[j][0] = fmaf(l, w.x, a[j][0]);
                a[j][1] = fmaf(l, w.y, a[j][1]);
            }
        }
        float bb0 = sm[OFF_B1W2 + hb],        bb1 = sm[OFF_B1W2 + hb + 1];
        float w20 = sm[OFF_B1W2 + MLPH + hb], w21 = sm[OFF_B1W2 + MLPH + hb + 1];
        #pragma unroll
        for (int j = 0; j < 7; j++) {
            float h0 = fmaxf(a[j][0] + bb0, 0.f) * w20;
            float h1 = fmaxf(a[j][1] + bb1, 0.f) * w21;
            *(float2*)&sm[OFF_H + (pkq * 7 + j) * MLPH + hb] = make_float2(h0, h1);
        }
    }
    __syncthreads();

    // ---- Phase 5: reduce, position weight, sigmoid ----
    if (tid < KPB && (key0 + tid) < n) {
        float s = b2[0];
        const float4* hp = (const float4*)&sm[OFF_H + tid * MLPH];
        float s1 = 0.f, s2 = 0.f, s3 = 0.f;
        #pragma unroll
        for (int j = 0; j < MLPH / 4; j++) {
            float4 v = hp[j];
            s += v.x; s1 += v.y; s2 += v.z; s3 += v.w;
        }
        s = (s + s1) + (s2 + s3);

        int p = pos[key0 + tid];
        float lp = log10f(fmaxf((float)p, 1.0f));
        float a0 = log1pf(expf(araw[0]));
        float a1 = log1pf(expf(araw[1]));
        float a2 = log1pf(expf(araw[2]));
        float w;
        if (lp < 3.f)      w = a0;
        else if (lp < 4.f) w = a0 + (a1 - a0) * (lp - 3.f);
        else if (lp < 5.f) w = a1 + (a2 - a1) * (lp - 4.f);
        else               w = a2;

        float z = s * w;
        out[key0 + tid] = 1.f / (1.f + expf(-z));
    }
}

extern "C" void kernel_launch(void* const* d_in, const int* in_sizes, int n_in,
                              void* d_out, int out_size) {
    const float* K      = (const float*)d_in[0];
    const int*   pos    = (const int*)  d_in[1];
    const float* ra     = (const float*)d_in[2];
    const float* mu     = (const float*)d_in[3];
    const float* kappa  = (const float*)d_in[4];
    const float* weight = (const float*)d_in[5];
    const float* bias   = (const float*)d_in[6];
    const float* W1     = (const float*)d_in[7];
    const float* b1     = (const float*)d_in[8];
    const float* W2     = (const float*)d_in[9];
    const float* b2     = (const float*)d_in[10];
    const float* araw   = (const float*)d_in[11];

    int n = in_sizes[1];   // number of keys

    static int smem_set = 0;
    if (!smem_set) {
        cudaFuncSetAttribute(key_pruning_main,
                             cudaFuncAttributeMaxDynamicSharedMemorySize, SMEM_BYTES);
        smem_set = 1;
    }

    precompute_fourier<<<(NBINS * NFREQ * 4 + 255) / 256, 256>>>(mu, kappa, weight, ra);

    int grid = (n + KPB - 1) / KPB;
    key_pruning_main<<<grid, TPB, SMEM_BYTES>>>((const float2*)K, pos, bias, W1, b1, W2, b2, araw,
                                                (float*)d_out, n);
}

// round 17
// speedup vs baseline: 1.8096x; 1.0192x over previous
#include <cuda_runtime.h>
#include <cuda_bf16.h>
#include <math.h>

#define NBINS 128
#define NFREQ 64
#define NKERN 3
#define MLPH  64
#define KPB   28   // keys per block -> grid 293; 2 blocks/SM
#define TPB   256

typedef unsigned long long ull;

// Planar coefficient table: g_C[f][coord][bin], coord 0..6 =
//   [A0, A1c, A1s, A2c, A2s, A3c, A3s]
// +1 f of zero padding so the double-buffer can read one f past the end.
__device__ float4 g_C4[(NFREQ + 1) * 7 * NBINS / 4];

__device__ __forceinline__ void fma2(ull& acc, ull a, ull b) {
    asm("fma.rn.f32x2 %0, %1, %2, %0;" : "+l"(acc) : "l"(a), "l"(b));
}
__device__ __forceinline__ ull dup2(float v) {
    ull r;
    asm("mov.b64 %0, {%1, %1};" : "=l"(r) : "f"(v));
    return r;
}
__device__ __forceinline__ float2 unpack2(ull v) {
    float2 r;
    asm("mov.b64 {%0, %1}, %2;" : "=f"(r.x), "=f"(r.y) : "l"(v));
    return r;
}
// 16B load with evict-last L1 policy (C lines shared with co-resident block).
__device__ __forceinline__ ulonglong2 ldg_el(const float* p) {
    ulonglong2 v;
    asm("ld.global.nc.L1::evict_last.v2.u64 {%0, %1}, [%2];"
        : "=l"(v.x), "=l"(v.y) : "l"(p));
    return v;
}

// Fast precompute: one (b,f,m) per thread in 4-lane groups, shuffle combine.
__global__ void precompute_fourier(const float* __restrict__ mu,
                                   const float* __restrict__ kappa,
                                   const float* __restrict__ weight,
                                   const float* __restrict__ ref_angles) {
    int t = blockIdx.x * blockDim.x + threadIdx.x;
    int pair = t >> 2;          // (b,f) index
    int m    = t & 3;           // kernel index; m==3 idle
    if (pair >= NBINS * NFREQ) return;
    int b = pair / NFREQ;
    int f = pair % NFREQ;

    float C[7];
    #pragma unroll
    for (int i = 0; i < 7; i++) C[i] = 0.f;

    if (m < NKERN) {
        int off = (b * NFREQ + f) * NKERN + m;
        float kp = kappa[off];
        float w  = weight[off];
        float me = mu[off] + ref_angles[f];
        float h  = 0.5f * kp;
        float h2 = h * h;
        float ek = __expf(-kp);
        float P0 = fmaf(h2, fmaf(h2, fmaf(h2, fmaf(h2, fmaf(h2, fmaf(h2,
                    1.9290123e-6f, 6.9444444e-5f), 1.7361111e-3f), 2.7777778e-2f),
                    0.25f), 1.0f), 1.0f);
        float P1 = fmaf(h2, fmaf(h2, fmaf(h2, fmaf(h2, fmaf(h2, fmaf(h2,
                    2.7557319e-7f, 1.1574074e-5f), 3.4722222e-4f), 6.9444444e-3f),
                    8.3333333e-2f), 0.5f), 1.0f);
        float P2 = fmaf(h2, fmaf(h2, fmaf(h2, fmaf(h2, fmaf(h2, fmaf(h2,
                    3.4446e-8f, 1.6534392e-6f), 5.7870370e-5f), 1.3888889e-3f),
                    2.0833333e-2f), 1.6666667e-1f), 0.5f);
        float P3 = fmaf(h2, fmaf(h2, fmaf(h2, fmaf(h2, fmaf(h2, fmaf(h2,
                    3.83e-9f, 2.0667e-7f), 8.2671958e-6f), 2.3148148e-4f),
                    4.1666667e-3f), 4.1666667e-2f), 1.6666667e-1f);
        float I0 = P0;
        float I1 = h * P1;
        float I2 = h2 * P2;
        float I3 = h2 * h * P3;

        float cm, sm;
        __sincosf(me, &sm, &cm);
        float wek = w * ek;
        C[0] = wek * I0;
        float g1 = 2.f * wek * I1;
        C[1] = g1 * cm;
        C[2] = g1 * sm;
        float c2 = cm * cm - sm * sm;
        float s2 = 2.f * cm * sm;
        float g2 = 2.f * wek * I2;
        C[3] = g2 * c2;
        C[4] = g2 * s2;
        float c3 = c2 * cm - s2 * sm;
        float s3 = s2 * cm + c2 * sm;
        float g3 = 2.f * wek * I3;
        C[5] = g3 * c3;
        C[6] = g3 * s3;
    }
    #pragma unroll
    for (int c = 0; c < 7; c++) {
        C[c] += __shfl_xor_sync(0xFFFFFFFF, C[c], 1);
        C[c] += __shfl_xor_sync(0xFFFFFFFF, C[c], 2);
    }
    if (m == 0) {
        float* gC = (float*)g_C4;
        #pragma unroll
        for (int c = 0; c < 7; c++)
            gC[(f * 7 + c) * NBINS + b] = C[c];
    }
}

// dynamic smem (floats):
//   sl[28*128] @ 0  (14336 B)
//   union @ 3584 floats:
//     phase 1/2: XA[64*28] float4 + XB[64*28] float4   (57344 B)
//     phase 3/4: w1T[128*66] + h[28*64] + b1w2[128]    (41472 B)
#define OFF_U    (KPB * NBINS)                 // 3584 floats
#define OFF_H    (OFF_U + 128 * 66)
#define OFF_B1W2 (OFF_H + KPB * MLPH)
#define SMEM_BYTES (OFF_U * 4 + 2 * NFREQ * KPB * 16)   // 71680

__global__ __launch_bounds__(TPB, 2)
void key_pruning_main(const float2* __restrict__ K2,
                      const int*    __restrict__ pos,
                      const float*  __restrict__ bias,
                      const float*  __restrict__ W1,      // [64][128]
                      const float*  __restrict__ b1,
                      const float*  __restrict__ W2,
                      const float*  __restrict__ b2,
                      const float*  __restrict__ araw,
                      float*        __restrict__ out,
                      int n) {
    extern __shared__ float sm[];
    float4* XA = (float4*)(sm + OFF_U);
    float4* XB = XA + NFREQ * KPB;

    const int tid  = threadIdx.x;
    const int warp = tid >> 5;
    const int lane = tid & 31;
    const int key0 = blockIdx.x * KPB;

    // ---- Phase 1: full 7-feature precompute per (f,key); recurrence done ONCE. ----
    for (int i = tid; i < KPB * NFREQ; i += TPB) {
        int kk = i / NFREQ;
        int f  = i & (NFREQ - 1);
        int key = key0 + kk; if (key >= n) key = n - 1;
        float2 v = K2[key * NFREQ + f];
        float r2 = fmaf(v.x, v.x, v.y * v.y);
        r2 = fmaxf(r2, 1e-30f);
        float rinv = rsqrtf(r2);
        float mag = r2 * rinv;              // xs0
        float c1x2 = 2.f * v.x * rinv;
        float xs3 = fmaf(c1x2, v.x, -mag);  // m*cos2
        float xs4 = c1x2 * v.y;             // m*sin2
        float xs5 = fmaf(c1x2, xs3, -v.x);  // m*cos3
        float xs6 = fmaf(c1x2, xs4, -v.y);  // m*sin3
        XA[f * KPB + kk] = make_float4(mag, v.x, v.y, xs3);
        XB[f * KPB + kk] = make_float4(xs4, xs5, xs6, 0.f);
    }
    __syncthreads();

    // ---- Phase 2: pure GEMM inner loop, double-buffered C. ----
    const int fbase = (warp >= 4) ? 32 : 0;
    const int wb    = (warp & 3) * 32;
    const int kq    = lane >> 3;
    const int b0    = wb + (lane & 7) * 4;   // thread bins b0..b0+3
    const int kbase = kq * 7;

    ull acc[14];
    #pragma unroll
    for (int i = 0; i < 14; i++) acc[i] = 0ull;

    const float* gC = (const float*)g_C4;
    const float* Cf = gC + fbase * 7 * NBINS + b0;

    ulonglong2 CA[7], CB[7];
    #pragma unroll
    for (int c = 0; c < 7; c++)
        CA[c] = ldg_el(Cf + c * NBINS);

    #define COMPUTE(BUF, FIDX) do {                                           \
        const int _f = (FIDX);                                                \
        _Pragma("unroll")                                                     \
        for (int j = 0; j < 7; j++) {                                         \
            float4 xa = XA[_f * KPB + kbase + j];                             \
            float4 xb = XB[_f * KPB + kbase + j];                             \
            ull* a = &acc[2 * j];                                             \
            { ull d = dup2(xa.x); fma2(a[0], d, BUF[0].x); fma2(a[1], d, BUF[0].y); } \
            { ull d = dup2(xa.y); fma2(a[0], d, BUF[1].x); fma2(a[1], d, BUF[1].y); } \
            { ull d = dup2(xa.z); fma2(a[0], d, BUF[2].x); fma2(a[1], d, BUF[2].y); } \
            { ull d = dup2(xa.w); fma2(a[0], d, BUF[3].x); fma2(a[1], d, BUF[3].y); } \
            { ull d = dup2(xb.x); fma2(a[0], d, BUF[4].x); fma2(a[1], d, BUF[4].y); } \
            { ull d = dup2(xb.y); fma2(a[0], d, BUF[5].x); fma2(a[1], d, BUF[5].y); } \
            { ull d = dup2(xb.z); fma2(a[0], d, BUF[6].x); fma2(a[1], d, BUF[6].y); } \
        }                                                                     \
    } while (0)

    for (int fo = 0; fo < 32; fo += 2) {
        const float* Cn1 = Cf + 7 * NBINS;     // f+1
        #pragma unroll
        for (int c = 0; c < 7; c++)
            CB[c] = ldg_el(Cn1 + c * NBINS);
        COMPUTE(CA, fbase + fo);

        const float* Cn2 = Cf + 14 * NBINS;    // f+2 (padded table: safe at end)
        #pragma unroll
        for (int c = 0; c < 7; c++)
            CA[c] = ldg_el(Cn2 + c * NBINS);
        COMPUTE(CB, fbase + fo + 1);

        Cf = Cn2;
    }
    #undef COMPUTE

    // f-split reduction into sl (low-f warps write with bias; high-f warps add)
    float4 bias4 = *(const float4*)&bias[b0];
    if (warp < 4) {
        #pragma unroll
        for (int j = 0; j < 7; j++) {
            float2 p0 = unpack2(acc[2 * j]);
            float2 p1 = unpack2(acc[2 * j + 1]);
            float4 o = make_float4(p0.x + bias4.x, p0.y + bias4.y,
                                   p1.x + bias4.z, p1.y + bias4.w);
            *(float4*)&sm[(kbase + j) * NBINS + b0] = o;
        }
    }
    __syncthreads();
    if (warp >= 4) {
        #pragma unroll
        for (int j = 0; j < 7; j++) {
            float2 p0 = unpack2(acc[2 * j]);
            float2 p1 = unpack2(acc[2 * j + 1]);
            float4 cur = *(float4*)&sm[(kbase + j) * NBINS + b0];
            cur.x += p0.x; cur.y += p0.y; cur.z += p1.x; cur.w += p1.y;
            *(float4*)&sm[(kbase + j) * NBINS + b0] = cur;
        }
    } else {
        // ---- Phase 3 (overlapped): stage transposed W1 [k][h], stride 66 ----
        for (int i = tid; i < MLPH * NBINS; i += 128) {
            int h = i >> 7;
            int k = i & 127;
            sm[OFF_U + k * 66 + h] = W1[i];
        }
        if (tid < MLPH) {
            sm[OFF_B1W2 + tid]        = b1[tid];
            sm[OFF_B1W2 + MLPH + tid] = W2[tid];
        }
    }
    __syncthreads();

    // ---- Phase 4: MLP layer 1 on 128 threads: 7 keys x 2 hidden per thread ----
    if (tid < 128) {
        int pkq = tid >> 5;            // key quarter (uniform per warp)
        int hb  = (tid & 31) * 2;      // hidden pair
        float a[7][2];
        #pragma unroll
        for (int j = 0; j < 7; j++) { a[j][0] = 0.f; a[j][1] = 0.f; }
        #pragma unroll 4
        for (int k = 0; k < NBINS; k++) {
            float2 w = *(const float2*)&sm[OFF_U + k * 66 + hb];
            #pragma unroll
            for (int j = 0; j < 7; j++) {
                float l = sm[(pkq * 7 + j) * NBINS + k];
                a[j][0] = fmaf(l, w.x, a[j][0]);
                a[j][1] = fmaf(l, w.y, a[j][1]);
            }
        }
        float bb0 = sm[OFF_B1W2 + hb],        bb1 = sm[OFF_B1W2 + hb + 1];
        float w20 = sm[OFF_B1W2 + MLPH + hb], w21 = sm[OFF_B1W2 + MLPH + hb + 1];
        #pragma unroll
        for (int j = 0; j < 7; j++) {
            float h0 = fmaxf(a[j][0] + bb0, 0.f) * w20;
            float h1 = fmaxf(a[j][1] + bb1, 0.f) * w21;
            *(float2*)&sm[OFF_H + (pkq * 7 + j) * MLPH + hb] = make_float2(h0, h1);
        }
    }
    __syncthreads();

    // ---- Phase 5: reduce, position weight, sigmoid ----
    if (tid < KPB && (key0 + tid) < n) {
        float s = b2[0];
        const float4* hp = (const float4*)&sm[OFF_H + tid * MLPH];
        float s1 = 0.f, s2 = 0.f, s3 = 0.f;
        #pragma unroll
        for (int j = 0; j < MLPH / 4; j++) {
            float4 v = hp[j];
            s += v.x; s1 += v.y; s2 += v.z; s3 += v.w;
        }
        s = (s + s1) + (s2 + s3);

        int p = pos[key0 + tid];
        float lp = log10f(fmaxf((float)p, 1.0f));
        float a0 = log1pf(expf(araw[0]));
        float a1 = log1pf(expf(araw[1]));
        float a2 = log1pf(expf(araw[2]));
        float w;
        if (lp < 3.f)      w = a0;
        else if (lp < 4.f) w = a0 + (a1 - a0) * (lp - 3.f);
        else if (lp < 5.f) w = a1 + (a2 - a1) * (lp - 4.f);
        else               w = a2;

        float z = s * w;
        out[key0 + tid] = 1.f / (1.f + expf(-z));
    }
}

extern "C" void kernel_launch(void* const* d_in, const int* in_sizes, int n_in,
                              void* d_out, int out_size) {
    const float* K      = (const float*)d_in[0];
    const int*   pos    = (const int*)  d_in[1];
    const float* ra     = (const float*)d_in[2];
    const float* mu     = (const float*)d_in[3];
    const float* kappa  = (const float*)d_in[4];
    const float* weight = (const float*)d_in[5];
    const float* bias   = (const float*)d_in[6];
    const float* W1     = (const float*)d_in[7];
    const float* b1     = (const float*)d_in[8];
    const float* W2     = (const float*)d_in[9];
    const float* b2     = (const float*)d_in[10];
    const float* araw   = (const float*)d_in[11];

    int n = in_sizes[1];   // number of keys

    static int smem_set = 0;
    if (!smem_set) {
        cudaFuncSetAttribute(key_pruning_main,
                             cudaFuncAttributeMaxDynamicSharedMemorySize, SMEM_BYTES);
        smem_set = 1;
    }

    precompute_fourier<<<(NBINS * NFREQ * 4 + 255) / 256, 256>>>(mu, kappa, weight, ra);

    int grid = (n + KPB - 1) / KPB;
    key_pruning_main<<<grid, TPB, SMEM_BYTES>>>((const float2*)K, pos, bias, W1, b1, W2, b2, araw,
                                                (float*)d_out, n);
}